// round 3
// baseline (speedup 1.0000x reference)
#include <cuda_runtime.h>
#include <cstdint>

#define BATCH   16384
#define NCONDS  50
#define EMB_DIM 64
#define IN_ROW  (1 + NCONDS)             // 51 int32 per batch row
#define OUT_ROW ((1 + NCONDS) * EMB_DIM) // 3264 floats per batch row

// One warp per batch row. Each 8-LANE GROUP (8 lanes x 8 floats) owns one
// condition -> 4 independent condition chains per warp, depth-3 reductions.
__global__ void __launch_bounds__(256)
cond_filter_kernel(const int* __restrict__ inp,
                   const float* __restrict__ table,
                   float* __restrict__ out)
{
    const int warp = (blockIdx.x * blockDim.x + threadIdx.x) >> 5;
    const int lane = threadIdx.x & 31;
    if (warp >= BATCH) return;

    const int g  = lane >> 3;   // group 0..3 (condition slot)
    const int hl = lane & 7;    // lane within group; owns dims [hl*8, hl*8+8)

    const int* __restrict__ row  = inp + (size_t)warp * IN_ROW;
    float* __restrict__     orow = out + (size_t)warp * OUT_ROW;

    // ---- Event embedding: every group loads the same row (L1 broadcast) ----
    const int eidx = __ldg(row);
    const float* erow = table + (size_t)eidx * EMB_DIM + hl * 8;
    const float4 ev0 = *reinterpret_cast<const float4*>(erow);
    const float4 ev1 = *reinterpret_cast<const float4*>(erow + 4);

    // Raw event embedding -> first 64 output floats (group 0 writes)
    if (g == 0) {
        *reinterpret_cast<float4*>(orow + hl * 8)     = ev0;
        *reinterpret_cast<float4*>(orow + hl * 8 + 4) = ev1;
    }

    float ss = ev0.x*ev0.x + ev0.y*ev0.y + ev0.z*ev0.z + ev0.w*ev0.w
             + ev1.x*ev1.x + ev1.y*ev1.y + ev1.z*ev1.z + ev1.w*ev1.w;
    #pragma unroll
    for (int o = 4; o; o >>= 1)
        ss += __shfl_xor_sync(0xffffffffu, ss, o);   // stays within 8-lane group
    const float einv = rsqrtf(ss);
    const float4 en0 = make_float4(ev0.x*einv, ev0.y*einv, ev0.z*einv, ev0.w*einv);
    const float4 en1 = make_float4(ev1.x*einv, ev1.y*einv, ev1.z*einv, ev1.w*einv);

    // ---- Conditions: 4 in flight per warp (one per 8-lane group) ----
    float* __restrict__ crow = orow + EMB_DIM;
    #pragma unroll 4
    for (int c0 = 0; c0 < 52; c0 += 4) {           // 13 iterations, 52 slots
        const int cond  = c0 + g;
        const int cc    = cond < NCONDS ? cond : NCONDS - 1;  // safe index
        const int cidx  = __ldg(row + 1 + cc);
        const float* cr = table + (size_t)cidx * EMB_DIM + hl * 8;
        const float4 cv0 = *reinterpret_cast<const float4*>(cr);
        const float4 cv1 = *reinterpret_cast<const float4*>(cr + 4);

        float s2 = cv0.x*cv0.x + cv0.y*cv0.y + cv0.z*cv0.z + cv0.w*cv0.w
                 + cv1.x*cv1.x + cv1.y*cv1.y + cv1.z*cv1.z + cv1.w*cv1.w;
        float dt = cv0.x*en0.x + cv0.y*en0.y + cv0.z*en0.z + cv0.w*en0.w
                 + cv1.x*en1.x + cv1.y*en1.y + cv1.z*en1.z + cv1.w*en1.w;
        #pragma unroll
        for (int o = 4; o; o >>= 1) {
            s2 += __shfl_xor_sync(0xffffffffu, s2, o);
            dt += __shfl_xor_sync(0xffffffffu, dt, o);
        }
        const float cinv  = rsqrtf(s2);
        // filtered = cond_nrm * score = cv * (dt * cinv^2)
        const float scale = dt * cinv * cinv;

        if (cond < NCONDS) {
            float* dst = crow + (size_t)cond * EMB_DIM + hl * 8;
            __stcs(reinterpret_cast<float4*>(dst),
                   make_float4(cv0.x*scale, cv0.y*scale, cv0.z*scale, cv0.w*scale));
            __stcs(reinterpret_cast<float4*>(dst + 4),
                   make_float4(cv1.x*scale, cv1.y*scale, cv1.z*scale, cv1.w*scale));
        }
    }
}

extern "C" void kernel_launch(void* const* d_in, const int* in_sizes, int n_in,
                              void* d_out, int out_size)
{
    const int*   inp   = (const int*)d_in[0];     // (16384, 51) int32
    const float* table = (const float*)d_in[1];   // (100002, 64) float32
    float*       out   = (float*)d_out;           // (16384, 3264) float32

    const int threads = 256;                 // 8 warps/block
    const int total_threads = BATCH * 32;    // one warp per row
    const int blocks = (total_threads + threads - 1) / threads;
    cond_filter_kernel<<<blocks, threads>>>(inp, table, out);
}

// round 5
// speedup vs baseline: 1.0078x; 1.0078x over previous
#include <cuda_runtime.h>
#include <cstdint>

#define BATCH   16384
#define NCONDS  50
#define EMB_DIM 64
#define NROWS   100002                    // NEVENTS + 2
#define IN_ROW  (1 + NCONDS)             // 51 int32 per batch row
#define OUT_ROW ((1 + NCONDS) * EMB_DIM) // 3264 floats per batch row

// Scratch: row-normalized copy of the event table (25.6 MB).
__device__ float g_ntab[(size_t)NROWS * EMB_DIM];

// ---------------- Kernel 1: normalize every table row once ----------------
// 8 lanes per row (8 floats each), 4 rows per warp, depth-3 reduction.
__global__ void __launch_bounds__(256)
norm_table_kernel(const float* __restrict__ table)
{
    const int warp = (blockIdx.x * blockDim.x + threadIdx.x) >> 5;
    const int lane = threadIdx.x & 31;
    const int g    = lane >> 3;          // row slot within warp (0..3)
    const int hl   = lane & 7;           // lane within row group
    const int row  = warp * 4 + g;
    if (row >= NROWS) return;

    const float* src = table + (size_t)row * EMB_DIM + hl * 8;
    const float4 v0 = *reinterpret_cast<const float4*>(src);
    const float4 v1 = *reinterpret_cast<const float4*>(src + 4);

    float ss = v0.x*v0.x + v0.y*v0.y + v0.z*v0.z + v0.w*v0.w
             + v1.x*v1.x + v1.y*v1.y + v1.z*v1.z + v1.w*v1.w;
    #pragma unroll
    for (int o = 4; o; o >>= 1)
        ss += __shfl_xor_sync(0xffffffffu, ss, o);   // within 8-lane group
    const float inv = rsqrtf(ss);

    float* dst = g_ntab + (size_t)row * EMB_DIM + hl * 8;
    *reinterpret_cast<float4*>(dst)     = make_float4(v0.x*inv, v0.y*inv, v0.z*inv, v0.w*inv);
    *reinterpret_cast<float4*>(dst + 4) = make_float4(v1.x*inv, v1.y*inv, v1.z*inv, v1.w*inv);
}

// ---------------- Kernel 2: gather + dot + scale (R2 layout) ----------------
// One warp per batch row; each half-warp (16 lanes x float4) owns one
// condition per iteration. Normalization is already folded into g_ntab:
//   filtered = cn * dot(e_n, cn)
__global__ void __launch_bounds__(256)
cond_filter_kernel(const int* __restrict__ inp,
                   const float* __restrict__ table,
                   float* __restrict__ out)
{
    const int warp = (blockIdx.x * blockDim.x + threadIdx.x) >> 5;
    const int lane = threadIdx.x & 31;
    if (warp >= BATCH) return;

    const int hl   = lane & 15;   // lane within half-warp
    const int half = lane >> 4;   // which half-warp (0/1)

    const int* __restrict__ row  = inp + (size_t)warp * IN_ROW;
    float* __restrict__     orow = out + (size_t)warp * OUT_ROW;

    // ---- Event: raw embedding to output, normalized version for the dot ----
    const int eidx = __ldg(row);
    const float4 ev = *reinterpret_cast<const float4*>(
        table + (size_t)eidx * EMB_DIM + hl * 4);
    if (half == 0)
        *reinterpret_cast<float4*>(orow + hl * 4) = ev;

    const float4 en = *reinterpret_cast<const float4*>(
        g_ntab + (size_t)eidx * EMB_DIM + hl * 4);

    // ---- Conditions: 2 per warp iteration (one per half-warp) ----
    float* __restrict__ crow = orow + EMB_DIM;
    #pragma unroll 5
    for (int c = 0; c < NCONDS; c += 2) {
        const int cidx = __ldg(row + 1 + c + half);
        const float4 cn = *reinterpret_cast<const float4*>(
            g_ntab + (size_t)cidx * EMB_DIM + hl * 4);

        float dt = cn.x * en.x + cn.y * en.y + cn.z * en.z + cn.w * en.w;
        #pragma unroll
        for (int o = 8; o; o >>= 1)
            dt += __shfl_xor_sync(0xffffffffu, dt, o);   // within half-warp

        // filtered = cond_nrm * score = cn * dot(e_n, cn)
        *reinterpret_cast<float4*>(crow + (size_t)(c + half) * EMB_DIM + hl * 4) =
            make_float4(cn.x * dt, cn.y * dt, cn.z * dt, cn.w * dt);
    }
}

extern "C" void kernel_launch(void* const* d_in, const int* in_sizes, int n_in,
                              void* d_out, int out_size)
{
    const int*   inp   = (const int*)d_in[0];     // (16384, 51) int32
    const float* table = (const float*)d_in[1];   // (100002, 64) float32
    float*       out   = (float*)d_out;           // (16384, 3264) float32

    // Pass 1: normalize table rows (32 rows per 256-thread block)
    const int nblocks = (NROWS + 31) / 32;
    norm_table_kernel<<<nblocks, 256>>>(table);

    // Pass 2: gather + filter
    const int threads = 256;
    const int total_threads = BATCH * 32;
    const int blocks = (total_threads + threads - 1) / threads;
    cond_filter_kernel<<<blocks, threads>>>(inp, table, out);
}

// round 6
// speedup vs baseline: 1.2264x; 1.2169x over previous
#include <cuda_runtime.h>
#include <cstdint>

#define BATCH   16384
#define NCONDS  50
#define EMB_DIM 64
#define IN_ROW  (1 + NCONDS)             // 51 int32 per batch row
#define OUT_ROW ((1 + NCONDS) * EMB_DIM) // 3264 floats per batch row
#define PF      4                        // software-pipeline depth
#define NSTAGE  (NCONDS / 2)             // 25 stages, 2 conds per stage

// One warp per batch row; each half-warp (16 lanes x float4) owns one
// condition per stage. Gathers are prefetched PF stages ahead through a
// register ring so each warp keeps ~PF loads in flight (breaks the
// load->shfl->load serial chain that bound earlier rounds).
__global__ void __launch_bounds__(256)
cond_filter_kernel(const int* __restrict__ inp,
                   const float* __restrict__ table,
                   float* __restrict__ out)
{
    const int warp = (blockIdx.x * blockDim.x + threadIdx.x) >> 5;
    const int lane = threadIdx.x & 31;
    if (warp >= BATCH) return;

    const int hl   = lane & 15;   // lane within half-warp
    const int half = lane >> 4;   // which half-warp (0/1)

    const int* __restrict__ row  = inp + (size_t)warp * IN_ROW;
    float* __restrict__     orow = out + (size_t)warp * OUT_ROW;

    // ---- Prologue: start PF gathers immediately, then do the event work ----
    float4 ring[PF];
    #pragma unroll
    for (int p = 0; p < PF; p++) {
        const int cidx = __ldg(row + 1 + 2 * p + half);
        ring[p] = *reinterpret_cast<const float4*>(
            table + (size_t)cidx * EMB_DIM + hl * 4);
    }

    // Event embedding: raw copy out + normalize in registers (overlaps
    // with the in-flight condition gathers above).
    const int eidx = __ldg(row);
    const float4 ev = *reinterpret_cast<const float4*>(
        table + (size_t)eidx * EMB_DIM + hl * 4);
    if (half == 0)
        *reinterpret_cast<float4*>(orow + hl * 4) = ev;

    float ss = ev.x * ev.x + ev.y * ev.y + ev.z * ev.z + ev.w * ev.w;
    #pragma unroll
    for (int o = 8; o; o >>= 1)
        ss += __shfl_xor_sync(0xffffffffu, ss, o);   // within half-warp
    const float einv = rsqrtf(ss);
    const float4 en = make_float4(ev.x * einv, ev.y * einv,
                                  ev.z * einv, ev.w * einv);

    // ---- Main pipeline: consume stage s, prefetch stage s+PF ----
    float* __restrict__ crow = orow + EMB_DIM;
    #pragma unroll
    for (int s = 0; s < NSTAGE; s++) {
        const float4 cv = ring[s % PF];

        if (s + PF < NSTAGE) {
            const int cidx = __ldg(row + 1 + 2 * (s + PF) + half);
            ring[s % PF] = *reinterpret_cast<const float4*>(
                table + (size_t)cidx * EMB_DIM + hl * 4);
        }

        float s2 = cv.x * cv.x + cv.y * cv.y + cv.z * cv.z + cv.w * cv.w;
        float dt = cv.x * en.x + cv.y * en.y + cv.z * en.z + cv.w * en.w;
        #pragma unroll
        for (int o = 8; o; o >>= 1) {
            s2 += __shfl_xor_sync(0xffffffffu, s2, o);
            dt += __shfl_xor_sync(0xffffffffu, dt, o);
        }
        const float cinv  = rsqrtf(s2);
        // filtered = cond_nrm * score = cv * (dt * cinv^2)
        const float scale = dt * cinv * cinv;

        *reinterpret_cast<float4*>(
            crow + (size_t)(2 * s + half) * EMB_DIM + hl * 4) =
            make_float4(cv.x * scale, cv.y * scale, cv.z * scale, cv.w * scale);
    }
}

extern "C" void kernel_launch(void* const* d_in, const int* in_sizes, int n_in,
                              void* d_out, int out_size)
{
    const int*   inp   = (const int*)d_in[0];     // (16384, 51) int32
    const float* table = (const float*)d_in[1];   // (100002, 64) float32
    float*       out   = (float*)d_out;           // (16384, 3264) float32

    const int threads = 256;                 // 8 warps/block
    const int total_threads = BATCH * 32;    // one warp per row
    const int blocks = (total_threads + threads - 1) / threads;
    cond_filter_kernel<<<blocks, threads>>>(inp, table, out);
}